// round 2
// baseline (speedup 1.0000x reference)
#include <cuda_runtime.h>
#include <cstdint>

// Problem constants
#define NS_PER   12500   // atoms per species
#define AEVD     1008
#define D1       256
#define D2       192
#define D3       160
#define ENS      8
#define NSPECIES 4
#define TM       128
#define NTILES   ((NS_PER + TM - 1) / TM)   // 98

// Shared memory layout (floats)
#define H_LD   264   // h buffer stride (256+8 pad, conflict-free)
#define A_LD   52    // A chunk stride (48+4 pad)
#define KB1    48    // layer1 K chunk
#define B1_LD  264   // layer1 B chunk stride
#define B2_LD  200   // layer2 B chunk stride (192+8)
#define B3_LD  168   // layer3 B chunk stride (160+8)

#define SM_H      (TM * H_LD)   // 33792
#define SM_A      (TM * A_LD)   // 6656
#define SM_B      12800         // max(48*264, 64*200, 64*168)
#define SM_FLOATS (SM_H + SM_A + SM_B + 128 + 256)
#define SMEM_BYTES (SM_FLOATS * 4)   // 214,528 bytes

__device__ double g_scratch;

__device__ __forceinline__ uint32_t f2tf32(float x) {
    uint32_t r;
    asm("cvt.rna.tf32.f32 %0, %1;" : "=r"(r) : "f"(x));
    return r;
}

__device__ __forceinline__ float celu01(float x) {
    // CELU with alpha = 0.1
    return x > 0.f ? x : 0.1f * (__expf(x * 10.f) - 1.f);
}

__device__ __forceinline__ void mma8(float d[4], const uint32_t a[4], const uint32_t b[2]) {
    asm volatile(
        "mma.sync.aligned.m16n8k8.row.col.f32.tf32.tf32.f32 "
        "{%0,%1,%2,%3},{%4,%5,%6,%7},{%8,%9},{%0,%1,%2,%3};\n"
        : "+f"(d[0]), "+f"(d[1]), "+f"(d[2]), "+f"(d[3])
        : "r"(a[0]), "r"(a[1]), "r"(a[2]), "r"(a[3]), "r"(b[0]), "r"(b[1]));
}

__global__ void __launch_bounds__(256, 1)
ani_fused_kernel(const float* __restrict__ aev,
                 const float* __restrict__ W1, const float* __restrict__ B1,
                 const float* __restrict__ W2, const float* __restrict__ B2,
                 const float* __restrict__ W3, const float* __restrict__ B3,
                 const float* __restrict__ W4, const float* __restrict__ B4,
                 const int*   __restrict__ idx)
{
    extern __shared__ float sm[];
    float* hbuf  = sm;                       // [128][264] activations
    float* As    = sm + SM_H;                // [128][52]  layer1 A chunk
    float* Bs    = As + SM_A;                // weight chunk buffer
    int*   rowIdx = (int*)(Bs + SM_B);       // [128]
    float* red   = (float*)(rowIdx + 128);   // [256]

    const int e    = blockIdx.x;
    const int tile = blockIdx.y;
    const int s    = blockIdx.z;
    const int se   = s * ENS + e;

    const int tid  = threadIdx.x;
    const int lane = tid & 31;
    const int warp = tid >> 5;
    const int gid  = lane >> 2;   // group id (0..7)
    const int tig  = lane & 3;    // thread in group (0..3)
    const int wm   = warp & 1;    // warp row (0..1)
    const int wn   = warp >> 1;   // warp col (0..3)
    const int mB   = wm * 64;

    const int tileBase = tile * TM;
    const int valid    = min(TM, NS_PER - tileBase);

    if (tid < TM)
        rowIdx[tid] = (tid < valid) ? idx[s * NS_PER + tileBase + tid] : -1;

    const float* W1g = W1 + (size_t)se * AEVD * D1;
    const float* W2g = W2 + (size_t)se * D1 * D2;
    const float* W3g = W3 + (size_t)se * D2 * D3;

    // ================= Layer 1: [128 x 1008] @ [1008 x 256] =================
    {
        const int nB = wn * 64;
        float acc[4][8][4];
        #pragma unroll
        for (int mi = 0; mi < 4; mi++)
            #pragma unroll
            for (int j = 0; j < 8; j++)
                #pragma unroll
                for (int q = 0; q < 4; q++) acc[mi][j][q] = 0.f;

        for (int kc = 0; kc < AEVD / KB1; ++kc) {   // 21 chunks
            __syncthreads();
            // Load A chunk (gathered rows), 128x48, tf32-rounded
            #pragma unroll
            for (int it = 0; it < 6; ++it) {
                int flat = tid + it * 256;          // < 1536 float4s
                int r  = flat / 12;
                int c4 = (flat % 12) * 4;
                int g  = rowIdx[r];
                float4 v = make_float4(0.f, 0.f, 0.f, 0.f);
                if (g >= 0)
                    v = *(const float4*)(aev + (size_t)g * AEVD + kc * KB1 + c4);
                float* d = As + r * A_LD + c4;
                d[0] = __uint_as_float(f2tf32(v.x));
                d[1] = __uint_as_float(f2tf32(v.y));
                d[2] = __uint_as_float(f2tf32(v.z));
                d[3] = __uint_as_float(f2tf32(v.w));
            }
            // Load B chunk: W1 rows [kc*48, kc*48+48) x 256
            #pragma unroll
            for (int it = 0; it < 12; ++it) {
                int flat = tid + it * 256;          // < 3072 float4s
                int kk = flat / 64;
                int c4 = (flat % 64) * 4;
                float4 v = *(const float4*)(W1g + (size_t)(kc * KB1 + kk) * D1 + c4);
                float* d = Bs + kk * B1_LD + c4;
                d[0] = __uint_as_float(f2tf32(v.x));
                d[1] = __uint_as_float(f2tf32(v.y));
                d[2] = __uint_as_float(f2tf32(v.z));
                d[3] = __uint_as_float(f2tf32(v.w));
            }
            __syncthreads();
            #pragma unroll
            for (int ks = 0; ks < KB1 / 8; ++ks) {  // 6 k-steps
                int k0 = ks * 8;
                uint32_t a[4][4];
                #pragma unroll
                for (int mi = 0; mi < 4; mi++) {
                    int r = mB + mi * 16 + gid;
                    a[mi][0] = __float_as_uint(As[r * A_LD + k0 + tig]);
                    a[mi][1] = __float_as_uint(As[(r + 8) * A_LD + k0 + tig]);
                    a[mi][2] = __float_as_uint(As[r * A_LD + k0 + tig + 4]);
                    a[mi][3] = __float_as_uint(As[(r + 8) * A_LD + k0 + tig + 4]);
                }
                #pragma unroll
                for (int j = 0; j < 8; j++) {
                    uint32_t b[2];
                    b[0] = __float_as_uint(Bs[(k0 + tig) * B1_LD + nB + j * 8 + gid]);
                    b[1] = __float_as_uint(Bs[(k0 + tig + 4) * B1_LD + nB + j * 8 + gid]);
                    #pragma unroll
                    for (int mi = 0; mi < 4; mi++) mma8(acc[mi][j], a[mi], b);
                }
            }
        }
        __syncthreads();
        // Epilogue: bias + CELU -> hbuf (tf32-rounded)
        const float* b1g = B1 + (size_t)se * D1;
        #pragma unroll
        for (int mi = 0; mi < 4; mi++) {
            int r0 = mB + mi * 16 + gid;
            #pragma unroll
            for (int j = 0; j < 8; j++) {
                int c = nB + j * 8 + tig * 2;
                float bb0 = b1g[c], bb1 = b1g[c + 1];
                hbuf[r0 * H_LD + c]           = __uint_as_float(f2tf32(celu01(acc[mi][j][0] + bb0)));
                hbuf[r0 * H_LD + c + 1]       = __uint_as_float(f2tf32(celu01(acc[mi][j][1] + bb1)));
                hbuf[(r0 + 8) * H_LD + c]     = __uint_as_float(f2tf32(celu01(acc[mi][j][2] + bb0)));
                hbuf[(r0 + 8) * H_LD + c + 1] = __uint_as_float(f2tf32(celu01(acc[mi][j][3] + bb1)));
            }
        }
    }

    // ================= Layer 2: [128 x 256] @ [256 x 192] =================
    {
        const int nB = wn * 48;
        float acc[4][6][4];
        #pragma unroll
        for (int mi = 0; mi < 4; mi++)
            #pragma unroll
            for (int j = 0; j < 6; j++)
                #pragma unroll
                for (int q = 0; q < 4; q++) acc[mi][j][q] = 0.f;

        for (int kc = 0; kc < 4; ++kc) {            // 4 chunks of K=64
            __syncthreads();
            #pragma unroll
            for (int it = 0; it < 12; ++it) {
                int flat = tid + it * 256;          // < 3072 float4s
                int kk = flat / 48;
                int c4 = (flat % 48) * 4;
                float4 v = *(const float4*)(W2g + (size_t)(kc * 64 + kk) * D2 + c4);
                float* d = Bs + kk * B2_LD + c4;
                d[0] = __uint_as_float(f2tf32(v.x));
                d[1] = __uint_as_float(f2tf32(v.y));
                d[2] = __uint_as_float(f2tf32(v.z));
                d[3] = __uint_as_float(f2tf32(v.w));
            }
            __syncthreads();
            #pragma unroll
            for (int ks = 0; ks < 8; ++ks) {
                int kg = kc * 64 + ks * 8;          // global k into h1
                int kl = ks * 8;                    // local k into Bs
                uint32_t a[4][4];
                #pragma unroll
                for (int mi = 0; mi < 4; mi++) {
                    int r = mB + mi * 16 + gid;
                    a[mi][0] = __float_as_uint(hbuf[r * H_LD + kg + tig]);
                    a[mi][1] = __float_as_uint(hbuf[(r + 8) * H_LD + kg + tig]);
                    a[mi][2] = __float_as_uint(hbuf[r * H_LD + kg + tig + 4]);
                    a[mi][3] = __float_as_uint(hbuf[(r + 8) * H_LD + kg + tig + 4]);
                }
                #pragma unroll
                for (int j = 0; j < 6; j++) {
                    uint32_t b[2];
                    b[0] = __float_as_uint(Bs[(kl + tig) * B2_LD + nB + j * 8 + gid]);
                    b[1] = __float_as_uint(Bs[(kl + tig + 4) * B2_LD + nB + j * 8 + gid]);
                    #pragma unroll
                    for (int mi = 0; mi < 4; mi++) mma8(acc[mi][j], a[mi], b);
                }
            }
        }
        __syncthreads();  // all reads of h1 done before overwrite
        const float* b2g = B2 + (size_t)se * D2;
        #pragma unroll
        for (int mi = 0; mi < 4; mi++) {
            int r0 = mB + mi * 16 + gid;
            #pragma unroll
            for (int j = 0; j < 6; j++) {
                int c = nB + j * 8 + tig * 2;
                float bb0 = b2g[c], bb1 = b2g[c + 1];
                hbuf[r0 * H_LD + c]           = __uint_as_float(f2tf32(celu01(acc[mi][j][0] + bb0)));
                hbuf[r0 * H_LD + c + 1]       = __uint_as_float(f2tf32(celu01(acc[mi][j][1] + bb1)));
                hbuf[(r0 + 8) * H_LD + c]     = __uint_as_float(f2tf32(celu01(acc[mi][j][2] + bb0)));
                hbuf[(r0 + 8) * H_LD + c + 1] = __uint_as_float(f2tf32(celu01(acc[mi][j][3] + bb1)));
            }
        }
    }

    // ================= Layer 3: [128 x 192] @ [192 x 160] =================
    {
        const int nB = wn * 40;
        float acc[4][5][4];
        #pragma unroll
        for (int mi = 0; mi < 4; mi++)
            #pragma unroll
            for (int j = 0; j < 5; j++)
                #pragma unroll
                for (int q = 0; q < 4; q++) acc[mi][j][q] = 0.f;

        for (int kc = 0; kc < 3; ++kc) {            // 3 chunks of K=64
            __syncthreads();
            #pragma unroll
            for (int it = 0; it < 10; ++it) {
                int flat = tid + it * 256;          // < 2560 float4s
                int kk = flat / 40;
                int c4 = (flat % 40) * 4;
                float4 v = *(const float4*)(W3g + (size_t)(kc * 64 + kk) * D3 + c4);
                float* d = Bs + kk * B3_LD + c4;
                d[0] = __uint_as_float(f2tf32(v.x));
                d[1] = __uint_as_float(f2tf32(v.y));
                d[2] = __uint_as_float(f2tf32(v.z));
                d[3] = __uint_as_float(f2tf32(v.w));
            }
            __syncthreads();
            #pragma unroll
            for (int ks = 0; ks < 8; ++ks) {
                int kg = kc * 64 + ks * 8;
                int kl = ks * 8;
                uint32_t a[4][4];
                #pragma unroll
                for (int mi = 0; mi < 4; mi++) {
                    int r = mB + mi * 16 + gid;
                    a[mi][0] = __float_as_uint(hbuf[r * H_LD + kg + tig]);
                    a[mi][1] = __float_as_uint(hbuf[(r + 8) * H_LD + kg + tig]);
                    a[mi][2] = __float_as_uint(hbuf[r * H_LD + kg + tig + 4]);
                    a[mi][3] = __float_as_uint(hbuf[(r + 8) * H_LD + kg + tig + 4]);
                }
                #pragma unroll
                for (int j = 0; j < 5; j++) {
                    uint32_t b[2];
                    b[0] = __float_as_uint(Bs[(kl + tig) * B3_LD + nB + j * 8 + gid]);
                    b[1] = __float_as_uint(Bs[(kl + tig + 4) * B3_LD + nB + j * 8 + gid]);
                    #pragma unroll
                    for (int mi = 0; mi < 4; mi++) mma8(acc[mi][j], a[mi], b);
                }
            }
        }
        __syncthreads();  // all reads of h2 done before overwrite
        const float* b3g = B3 + (size_t)se * D3;
        #pragma unroll
        for (int mi = 0; mi < 4; mi++) {
            int r0 = mB + mi * 16 + gid;
            #pragma unroll
            for (int j = 0; j < 5; j++) {
                int c = nB + j * 8 + tig * 2;
                float bb0 = b3g[c], bb1 = b3g[c + 1];
                hbuf[r0 * H_LD + c]           = celu01(acc[mi][j][0] + bb0);
                hbuf[r0 * H_LD + c + 1]       = celu01(acc[mi][j][1] + bb1);
                hbuf[(r0 + 8) * H_LD + c]     = celu01(acc[mi][j][2] + bb0);
                hbuf[(r0 + 8) * H_LD + c + 1] = celu01(acc[mi][j][3] + bb1);
            }
        }
    }

    // ========== Layer 4 + reduction: sum_m (h3 . w4) + valid*b4 ==========
    __syncthreads();
    float v = 0.f;
    if (tid < D3) {
        float cs = 0.f;
        for (int r = 0; r < valid; ++r) cs += hbuf[r * H_LD + tid];
        v = cs * W4[(size_t)se * D3 + tid];
    }
    red[tid] = v;
    __syncthreads();
    #pragma unroll
    for (int st = 128; st > 0; st >>= 1) {
        if (tid < st) red[tid] += red[tid + st];
        __syncthreads();
    }
    if (tid == 0)
        atomicAdd(&g_scratch, (double)(red[0] + (float)valid * B4[se]));
}

__global__ void init_kernel() { g_scratch = 0.0; }

__global__ void fin_kernel(float* out) { out[0] = (float)(g_scratch * (1.0 / ENS)); }

extern "C" void kernel_launch(void* const* d_in, const int* in_sizes, int n_in,
                              void* d_out, int out_size)
{
    // Identify inputs by element count (robust to metadata ordering).
    // aev=50,400,000  W1=8,257,536  b1=8,192  W2=1,572,864  b2=6,144
    // W3=983,040  b3=5,120  W4=5,120  b4=32  species=50,000  idx=50,000
    // Ties: b3 precedes W4; species precedes idx (true in both plausible orders).
    const float *aev = 0, *W1 = 0, *B1 = 0, *W2 = 0, *B2 = 0,
                *W3 = 0, *B3 = 0, *W4 = 0, *B4 = 0;
    const int *idx = 0;
    int n5120 = 0, n50000 = 0;
    for (int i = 0; i < n_in; ++i) {
        switch (in_sizes[i]) {
            case 50400000: aev = (const float*)d_in[i]; break;
            case 8257536:  W1  = (const float*)d_in[i]; break;
            case 8192:     B1  = (const float*)d_in[i]; break;
            case 1572864:  W2  = (const float*)d_in[i]; break;
            case 6144:     B2  = (const float*)d_in[i]; break;
            case 983040:   W3  = (const float*)d_in[i]; break;
            case 5120:
                if (n5120++ == 0) B3 = (const float*)d_in[i];
                else              W4 = (const float*)d_in[i];
                break;
            case 32:       B4  = (const float*)d_in[i]; break;
            case 50000:
                if (n50000++ == 0) { /* species (unused) */ }
                else idx = (const int*)d_in[i];
                break;
            default: break;
        }
    }

    cudaFuncSetAttribute(ani_fused_kernel,
                         cudaFuncAttributeMaxDynamicSharedMemorySize, SMEM_BYTES);

    init_kernel<<<1, 1>>>();
    dim3 grid(ENS, NTILES, NSPECIES);   // e fastest -> AEV rows reused in L2
    ani_fused_kernel<<<grid, 256, SMEM_BYTES>>>(aev, W1, B1, W2, B2, W3, B3, W4, B4, idx);
    fin_kernel<<<1, 1>>>((float*)d_out);
}